// round 3
// baseline (speedup 1.0000x reference)
#include <cuda_runtime.h>
#include <math.h>
#include <stdint.h>

// ---------------- problem constants ----------------
#define Bq   8
#define SPq  800
#define SSq  48
#define NTq  848          // SP + SS
#define DPq  2048
#define DSq  1024
#define DCq  1024
#define Hq   8
#define HDq  256
#define FPq  16384
#define FSq  4096
#define EPSq 1e-6f
#define MASKV (-2.3819763e+38f)

static constexpr size_t NPROW = (size_t)Bq * SPq;   // 6400 prefix rows
static constexpr size_t NSROW = (size_t)Bq * SSq;   // 384 suffix rows

// ---------------- scratch layout (single __device__ global) ----------------
static constexpr size_t O_HP   = 0;                                  // [6400,2048] gemma-norm(prefix)
static constexpr size_t O_HS   = O_HP   + NPROW * DPq;               // [384,1024]  ada-norm(suffix)
static constexpr size_t O_MOD1 = O_HS   + NSROW * DSq;               // [8,3072]
static constexpr size_t O_MOD2 = O_MOD1 + (size_t)Bq * 3 * DSq;      // [8,3072]
static constexpr size_t O_QP   = O_MOD2 + (size_t)Bq * 3 * DSq;      // [6400,2048]
static constexpr size_t O_QS   = O_QP   + NPROW * (size_t)(Hq*HDq);  // [384,2048]
static constexpr size_t O_KP   = O_QS   + NSROW * (size_t)(Hq*HDq);  // [6400,256]
static constexpr size_t O_KS   = O_KP   + NPROW * HDq;               // [384,256]
static constexpr size_t O_VP   = O_KS   + NSROW * HDq;               // [6400,256]
static constexpr size_t O_VS   = O_VP   + NPROW * HDq;               // [384,256]
static constexpr size_t O_Q    = O_VS   + NSROW * HDq;               // [B*H,848,256] roped
static constexpr size_t O_K    = O_Q    + (size_t)Bq*Hq*NTq*HDq;     // [B,848,256]   roped
static constexpr size_t O_VT   = O_K    + (size_t)Bq*NTq*HDq;        // [B,256,848]   v transposed
static constexpr size_t O_SC   = O_VT   + (size_t)Bq*NTq*HDq;        // [B*H,848,848] scores
static constexpr size_t O_AP   = O_SC   + (size_t)Bq*Hq*NTq*NTq;     // [6400,2048] attn out prefix
static constexpr size_t O_AS   = O_AP   + NPROW * (size_t)(Hq*HDq);  // [384,2048]  attn out suffix
static constexpr size_t O_RESP = O_AS   + NSROW * (size_t)(Hq*HDq);  // [6400,2048]
static constexpr size_t O_HP2  = O_RESP + NPROW * DPq;               // [6400,2048]
static constexpr size_t O_RESS = O_HP2  + NPROW * DPq;               // [384,1024]
static constexpr size_t O_H2S  = O_RESS + NSROW * DSq;               // [384,1024]
static constexpr size_t O_UP   = O_H2S  + NSROW * DSq;               // [6400,16384]
static constexpr size_t O_HPM  = O_UP   + NPROW * FPq;               // [6400,16384]
static constexpr size_t O_US   = O_HPM  + NPROW * FPq;               // [384,4096]
static constexpr size_t O_HSM  = O_US   + NSROW * FSq;               // [384,4096]
static constexpr size_t SCR_TOTAL = O_HSM + NSROW * FSq;             // ~348M floats

__device__ float g_scr[SCR_TOTAL];

// ---------------- helpers ----------------
__device__ __forceinline__ float gelu_tanh(float x) {
    float x3 = x * x * x;
    return 0.5f * x * (1.0f + tanhf(0.7978845608028654f * (x + 0.044715f * x3)));
}

struct EpiParams {
    const float* resid;  // mode 4,5
    const float* gate;   // mode 5
    const float* umat;   // mode 6
    const float* bias;   // mode 3
    float* outp;         // mode 2
    float* outs;         // mode 2
    float scale;         // mode 1
    int ldg;             // mode 5
    int rpb;             // mode 5
};

// ---------------- generic NT GEMM: C[M,N] = A[M,K] @ B[N,K]^T (+epilogue) ----
// Modes: 0 plain; 1 attn scores (scale+mask); 2 PV scatter; 3 +bias;
//        4 +resid; 5 resid + acc*gate; 6 gelu(acc)*U
template <int MODE>
__global__ void __launch_bounds__(256) gemm_nt(
    const float* __restrict__ Ag, const float* __restrict__ Bg,
    float* __restrict__ Cg, int M, int N, int K,
    long long sAz, long long sBz, int bDivB, long long sCz, EpiParams ep)
{
    __shared__ float As[8][128];
    __shared__ float Bs[8][128];

    int z = blockIdx.z;
    const float* A = Ag + (size_t)z * (size_t)sAz;
    const float* B = Bg + (size_t)(z / bDivB) * (size_t)sBz;
    float* C = Cg ? (Cg + (size_t)z * (size_t)sCz) : nullptr;

    int m0 = blockIdx.y * 128;
    int n0 = blockIdx.x * 128;
    int tid = threadIdx.x;
    int tx = tid & 15, ty = tid >> 4;

    int ldRow = tid >> 1;          // 0..127
    int ldCol = (tid & 1) * 4;     // 0 or 4

    float acc[8][8];
#pragma unroll
    for (int i = 0; i < 8; i++)
#pragma unroll
        for (int j = 0; j < 8; j++) acc[i][j] = 0.0f;

    for (int k0 = 0; k0 < K; k0 += 8) {
        float4 av = make_float4(0.f, 0.f, 0.f, 0.f);
        int gr = m0 + ldRow;
        if (gr < M) av = *reinterpret_cast<const float4*>(A + (size_t)gr * K + k0 + ldCol);
        As[ldCol + 0][ldRow] = av.x; As[ldCol + 1][ldRow] = av.y;
        As[ldCol + 2][ldRow] = av.z; As[ldCol + 3][ldRow] = av.w;

        float4 bv = make_float4(0.f, 0.f, 0.f, 0.f);
        int gn = n0 + ldRow;
        if (gn < N) bv = *reinterpret_cast<const float4*>(B + (size_t)gn * K + k0 + ldCol);
        Bs[ldCol + 0][ldRow] = bv.x; Bs[ldCol + 1][ldRow] = bv.y;
        Bs[ldCol + 2][ldRow] = bv.z; Bs[ldCol + 3][ldRow] = bv.w;
        __syncthreads();

#pragma unroll
        for (int kk = 0; kk < 8; kk++) {
            float a[8], b[8];
#pragma unroll
            for (int i = 0; i < 8; i++) a[i] = As[kk][ty * 8 + i];
#pragma unroll
            for (int j = 0; j < 8; j++) b[j] = Bs[kk][tx * 8 + j];
#pragma unroll
            for (int i = 0; i < 8; i++)
#pragma unroll
                for (int j = 0; j < 8; j++) acc[i][j] += a[i] * b[j];
        }
        __syncthreads();
    }

#pragma unroll
    for (int i = 0; i < 8; i++) {
        int r = m0 + ty * 8 + i;
        if (r >= M) continue;
#pragma unroll
        for (int j = 0; j < 8; j++) {
            int c = n0 + tx * 8 + j;
            if (c >= N) continue;
            float v = acc[i][j];
            size_t idx = (size_t)r * N + c;
            if constexpr (MODE == 0) {
                C[idx] = v;
            } else if constexpr (MODE == 1) {
                float msk = (r < SPq && c >= SPq) ? MASKV : 0.0f;
                C[idx] = v * ep.scale + msk;
            } else if constexpr (MODE == 2) {
                int b_ = z / bDivB, h_ = z % bDivB;
                if (r < SPq)
                    ep.outp[((size_t)b_ * SPq + r) * (Hq * HDq) + h_ * HDq + c] = v;
                else
                    ep.outs[((size_t)b_ * SSq + (r - SPq)) * (Hq * HDq) + h_ * HDq + c] = v;
            } else if constexpr (MODE == 3) {
                C[idx] = v + ep.bias[c];
            } else if constexpr (MODE == 4) {
                C[idx] = ep.resid[idx] + v;
            } else if constexpr (MODE == 5) {
                C[idx] = ep.resid[idx] + v * ep.gate[(size_t)(r / ep.rpb) * ep.ldg + c];
            } else if constexpr (MODE == 6) {
                C[idx] = gelu_tanh(v) * ep.umat[idx];
            }
        }
    }
}

// ---------------- norms ----------------
__global__ void rmsnorm_gemma_k(const float* __restrict__ x, const float* __restrict__ w,
                                float* __restrict__ out, int D)
{
    int row = blockIdx.x;
    const float* xr = x + (size_t)row * D;
    float ss = 0.0f;
    for (int c = threadIdx.x; c < D; c += 256) { float v = xr[c]; ss += v * v; }
    __shared__ float red[256];
    red[threadIdx.x] = ss; __syncthreads();
    for (int s = 128; s > 0; s >>= 1) {
        if (threadIdx.x < s) red[threadIdx.x] += red[threadIdx.x + s];
        __syncthreads();
    }
    float rinv = rsqrtf(red[0] / (float)D + EPSq);
    float* orow = out + (size_t)row * D;
    for (int c = threadIdx.x; c < D; c += 256)
        orow[c] = xr[c] * rinv * (1.0f + w[c]);
}

__global__ void ada_norm_k(const float* __restrict__ x, const float* __restrict__ mod,
                           float* __restrict__ out, int D, int rowsPerB)
{
    int row = blockIdx.x;
    int b = row / rowsPerB;
    const float* xr = x + (size_t)row * D;
    float ss = 0.0f;
    for (int c = threadIdx.x; c < D; c += 256) { float v = xr[c]; ss += v * v; }
    __shared__ float red[256];
    red[threadIdx.x] = ss; __syncthreads();
    for (int s = 128; s > 0; s >>= 1) {
        if (threadIdx.x < s) red[threadIdx.x] += red[threadIdx.x + s];
        __syncthreads();
    }
    float rinv = rsqrtf(red[0] / (float)D + EPSq);
    const float* mb = mod + (size_t)b * 3 * D;
    float* orow = out + (size_t)row * D;
    for (int c = threadIdx.x; c < D; c += 256) {
        float scale = mb[c], shift = mb[D + c];
        orow[c] = xr[c] * rinv * (1.0f + scale) + shift;
    }
}

// ---------------- rope / transpose ----------------
__global__ void rope_q_k(const float* __restrict__ qp, const float* __restrict__ qs,
                         float* __restrict__ q)
{
    size_t idx = (size_t)blockIdx.x * blockDim.x + threadIdx.x;
    const size_t total = (size_t)Bq * NTq * Hq * (HDq / 2);
    if (idx >= total) return;
    int d = (int)(idx % (HDq / 2)); size_t t = idx / (HDq / 2);
    int h = (int)(t % Hq); t /= Hq;
    int n = (int)(t % NTq); int b = (int)(t / NTq);
    const float* src = (n < SPq)
        ? qp + ((size_t)b * SPq + n) * (Hq * HDq) + h * HDq
        : qs + ((size_t)b * SSq + (n - SPq)) * (Hq * HDq) + h * HDq;
    float x1 = src[d], x2 = src[d + 128];
    float invf = powf(10000.0f, -(float)d * (1.0f / 128.0f));
    float ang = (float)n * invf;
    float cs = cosf(ang), sn = sinf(ang);
    float* dst = q + (((size_t)b * Hq + h) * NTq + n) * HDq;
    dst[d] = x1 * cs - x2 * sn;
    dst[d + 128] = x2 * cs + x1 * sn;
}

__global__ void rope_k_k(const float* __restrict__ kp, const float* __restrict__ ks,
                         float* __restrict__ k)
{
    size_t idx = (size_t)blockIdx.x * blockDim.x + threadIdx.x;
    const size_t total = (size_t)Bq * NTq * (HDq / 2);
    if (idx >= total) return;
    int d = (int)(idx % (HDq / 2)); size_t t = idx / (HDq / 2);
    int n = (int)(t % NTq); int b = (int)(t / NTq);
    const float* src = (n < SPq)
        ? kp + ((size_t)b * SPq + n) * HDq
        : ks + ((size_t)b * SSq + (n - SPq)) * HDq;
    float x1 = src[d], x2 = src[d + 128];
    float invf = powf(10000.0f, -(float)d * (1.0f / 128.0f));
    float ang = (float)n * invf;
    float cs = cosf(ang), sn = sinf(ang);
    float* dst = k + ((size_t)b * NTq + n) * HDq;
    dst[d] = x1 * cs - x2 * sn;
    dst[d + 128] = x2 * cs + x1 * sn;
}

__global__ void transpose_v_k(const float* __restrict__ vp, const float* __restrict__ vs,
                              float* __restrict__ vt)
{
    size_t idx = (size_t)blockIdx.x * blockDim.x + threadIdx.x;
    const size_t total = (size_t)Bq * NTq * HDq;
    if (idx >= total) return;
    int d = (int)(idx % HDq); size_t t = idx / HDq;
    int n = (int)(t % NTq); int b = (int)(t / NTq);
    float v = (n < SPq)
        ? vp[((size_t)b * SPq + n) * HDq + d]
        : vs[((size_t)b * SSq + (n - SPq)) * HDq + d];
    vt[((size_t)b * HDq + d) * NTq + n] = v;
}

// ---------------- softmax (row-wise, fp32) ----------------
__global__ void softmax_k(float* __restrict__ s, int L)
{
    float* row = s + (size_t)blockIdx.x * L;
    __shared__ float red[256];
    float mx = -INFINITY;
    for (int c = threadIdx.x; c < L; c += 256) mx = fmaxf(mx, row[c]);
    red[threadIdx.x] = mx; __syncthreads();
    for (int st = 128; st > 0; st >>= 1) {
        if (threadIdx.x < st) red[threadIdx.x] = fmaxf(red[threadIdx.x], red[threadIdx.x + st]);
        __syncthreads();
    }
    mx = red[0]; __syncthreads();
    float sum = 0.0f;
    for (int c = threadIdx.x; c < L; c += 256) {
        float e = expf(row[c] - mx);
        row[c] = e; sum += e;
    }
    red[threadIdx.x] = sum; __syncthreads();
    for (int st = 128; st > 0; st >>= 1) {
        if (threadIdx.x < st) red[threadIdx.x] += red[threadIdx.x + st];
        __syncthreads();
    }
    float inv = 1.0f / red[0];
    for (int c = threadIdx.x; c < L; c += 256) row[c] *= inv;
}

// ---------------- host-side GEMM dispatch ----------------
static void run_gemm(int mode, const float* A, const float* B, float* C,
                     int M, int N, int K,
                     long long sAz, long long sBz, int bDivB, long long sCz,
                     int Z, EpiParams ep)
{
    dim3 grid((N + 127) / 128, (M + 127) / 128, Z);
    switch (mode) {
        case 0: gemm_nt<0><<<grid, 256>>>(A, B, C, M, N, K, sAz, sBz, bDivB, sCz, ep); break;
        case 1: gemm_nt<1><<<grid, 256>>>(A, B, C, M, N, K, sAz, sBz, bDivB, sCz, ep); break;
        case 2: gemm_nt<2><<<grid, 256>>>(A, B, C, M, N, K, sAz, sBz, bDivB, sCz, ep); break;
        case 3: gemm_nt<3><<<grid, 256>>>(A, B, C, M, N, K, sAz, sBz, bDivB, sCz, ep); break;
        case 4: gemm_nt<4><<<grid, 256>>>(A, B, C, M, N, K, sAz, sBz, bDivB, sCz, ep); break;
        case 5: gemm_nt<5><<<grid, 256>>>(A, B, C, M, N, K, sAz, sBz, bDivB, sCz, ep); break;
        case 6: gemm_nt<6><<<grid, 256>>>(A, B, C, M, N, K, sAz, sBz, bDivB, sCz, ep); break;
    }
}

extern "C" void kernel_launch(void* const* d_in, const int* in_sizes, int n_in,
                              void* d_out, int out_size)
{
    const float* prefix_x    = (const float*)d_in[0];
    const float* suffix_x    = (const float*)d_in[1];
    const float* cond        = (const float*)d_in[2];
    const float* p_ln_w      = (const float*)d_in[3];
    const float* p_q_w       = (const float*)d_in[4];
    const float* p_k_w       = (const float*)d_in[5];
    const float* p_v_w       = (const float*)d_in[6];
    const float* p_o_w       = (const float*)d_in[7];
    const float* p_post_ln_w = (const float*)d_in[8];
    const float* p_gate_w    = (const float*)d_in[9];
    const float* p_up_w      = (const float*)d_in[10];
    const float* p_down_w    = (const float*)d_in[11];
    const float* s_ada1_w    = (const float*)d_in[12];
    const float* s_ada1_b    = (const float*)d_in[13];
    const float* s_q_w       = (const float*)d_in[14];
    const float* s_k_w       = (const float*)d_in[15];
    const float* s_v_w       = (const float*)d_in[16];
    const float* s_o_w       = (const float*)d_in[17];
    const float* s_ada2_w    = (const float*)d_in[18];
    const float* s_ada2_b    = (const float*)d_in[19];
    const float* s_gate_w    = (const float*)d_in[20];
    const float* s_up_w      = (const float*)d_in[21];
    const float* s_down_w    = (const float*)d_in[22];
    // d_in[23] position_ids (arange, recomputed), d_in[24] attn_mask (deterministic) unused

    float* scr = nullptr;
    cudaGetSymbolAddress((void**)&scr, g_scr);

    float* hp    = scr + O_HP;
    float* hs    = scr + O_HS;
    float* mod1  = scr + O_MOD1;
    float* mod2  = scr + O_MOD2;
    float* qp    = scr + O_QP;
    float* qs    = scr + O_QS;
    float* kp    = scr + O_KP;
    float* ks    = scr + O_KS;
    float* vp    = scr + O_VP;
    float* vs    = scr + O_VS;
    float* q     = scr + O_Q;
    float* k     = scr + O_K;
    float* vt    = scr + O_VT;
    float* sc    = scr + O_SC;
    float* ap    = scr + O_AP;
    float* as_   = scr + O_AS;
    float* res_p = scr + O_RESP;
    float* hp2   = scr + O_HP2;
    float* res_s = scr + O_RESS;
    float* h2s   = scr + O_H2S;
    float* Up    = scr + O_UP;
    float* Hp    = scr + O_HPM;
    float* Us    = scr + O_US;
    float* Hs    = scr + O_HSM;

    float* outp = (float*)d_out;
    float* outs = outp + NPROW * DPq;

    EpiParams ep0 = {};

    // 1) norms + ada modulation
    rmsnorm_gemma_k<<<(int)NPROW, 256>>>(prefix_x, p_ln_w, hp, DPq);
    { EpiParams e = ep0; e.bias = s_ada1_b;
      run_gemm(3, cond, s_ada1_w, mod1, Bq, 3 * DSq, DCq, 0, 0, 1, 0, 1, e); }
    ada_norm_k<<<(int)NSROW, 256>>>(suffix_x, mod1, hs, DSq, SSq);

    // 2) QKV projections
    run_gemm(0, hp, p_q_w, qp, (int)NPROW, Hq * HDq, DPq, 0, 0, 1, 0, 1, ep0);
    run_gemm(0, hp, p_k_w, kp, (int)NPROW, HDq,      DPq, 0, 0, 1, 0, 1, ep0);
    run_gemm(0, hp, p_v_w, vp, (int)NPROW, HDq,      DPq, 0, 0, 1, 0, 1, ep0);
    run_gemm(0, hs, s_q_w, qs, (int)NSROW, Hq * HDq, DSq, 0, 0, 1, 0, 1, ep0);
    run_gemm(0, hs, s_k_w, ks, (int)NSROW, HDq,      DSq, 0, 0, 1, 0, 1, ep0);
    run_gemm(0, hs, s_v_w, vs, (int)NSROW, HDq,      DSq, 0, 0, 1, 0, 1, ep0);

    // 3) RoPE + layouts
    {
        size_t tq = (size_t)Bq * NTq * Hq * (HDq / 2);
        rope_q_k<<<(int)((tq + 255) / 256), 256>>>(qp, qs, q);
        size_t tk = (size_t)Bq * NTq * (HDq / 2);
        rope_k_k<<<(int)((tk + 255) / 256), 256>>>(kp, ks, k);
        size_t tv = (size_t)Bq * NTq * HDq;
        transpose_v_k<<<(int)((tv + 255) / 256), 256>>>(vp, vs, vt);
    }

    // 4) attention
    { EpiParams e = ep0; e.scale = 0.0625f;  // HD^-0.5
      run_gemm(1, q, k, sc, NTq, NTq, HDq,
               (long long)NTq * HDq, (long long)NTq * HDq, Hq,
               (long long)NTq * NTq, Bq * Hq, e); }
    softmax_k<<<Bq * Hq * NTq, 256>>>(sc, NTq);
    { EpiParams e = ep0; e.outp = ap; e.outs = as_;
      run_gemm(2, sc, vt, nullptr, NTq, HDq, NTq,
               (long long)NTq * NTq, (long long)HDq * NTq, Hq, 0, Bq * Hq, e); }

    // 5) prefix: o-proj + residual, post-norm, MLP
    { EpiParams e = ep0; e.resid = prefix_x;
      run_gemm(4, ap, p_o_w, res_p, (int)NPROW, DPq, Hq * HDq, 0, 0, 1, 0, 1, e); }
    rmsnorm_gemma_k<<<(int)NPROW, 256>>>(res_p, p_post_ln_w, hp2, DPq);
    run_gemm(0, hp2, p_up_w, Up, (int)NPROW, FPq, DPq, 0, 0, 1, 0, 1, ep0);
    { EpiParams e = ep0; e.umat = Up;
      run_gemm(6, hp2, p_gate_w, Hp, (int)NPROW, FPq, DPq, 0, 0, 1, 0, 1, e); }
    { EpiParams e = ep0; e.resid = res_p;
      run_gemm(4, Hp, p_down_w, outp, (int)NPROW, DPq, FPq, 0, 0, 1, 0, 1, e); }

    // 6) suffix: gated o-proj + residual, ada-norm2, gated MLP
    { EpiParams e = ep0; e.resid = suffix_x; e.gate = mod1 + 2 * DSq; e.ldg = 3 * DSq; e.rpb = SSq;
      run_gemm(5, as_, s_o_w, res_s, (int)NSROW, DSq, Hq * HDq, 0, 0, 1, 0, 1, e); }
    { EpiParams e = ep0; e.bias = s_ada2_b;
      run_gemm(3, cond, s_ada2_w, mod2, Bq, 3 * DSq, DCq, 0, 0, 1, 0, 1, e); }
    ada_norm_k<<<(int)NSROW, 256>>>(res_s, mod2, h2s, DSq, SSq);
    run_gemm(0, h2s, s_up_w, Us, (int)NSROW, FSq, DSq, 0, 0, 1, 0, 1, ep0);
    { EpiParams e = ep0; e.umat = Us;
      run_gemm(6, h2s, s_gate_w, Hs, (int)NSROW, FSq, DSq, 0, 0, 1, 0, 1, e); }
    { EpiParams e = ep0; e.resid = res_s; e.gate = mod2 + 2 * DSq; e.ldg = 3 * DSq; e.rpb = SSq;
      run_gemm(5, Hs, s_down_w, outs, (int)NSROW, DSq, FSq, 0, 0, 1, 0, 1, e); }
}

// round 7
// speedup vs baseline: 2.1775x; 2.1775x over previous
#include <cuda_runtime.h>
#include <cuda_bf16.h>
#include <math.h>
#include <stdint.h>

// ---------------- problem constants ----------------
#define Bq   8
#define SPq  800
#define SSq  48
#define NTq  848
#define DPq  2048
#define DSq  1024
#define DCq  1024
#define Hq   8
#define HDq  256
#define FPq  16384
#define FSq  4096
#define EPSq 1e-6f
#define MASKV (-2.3819763e+38f)

static constexpr size_t NPROW = (size_t)Bq * SPq;   // 6400
static constexpr size_t NSROW = (size_t)Bq * SSq;   // 384

// ---------------- scratch layout ----------------
static constexpr size_t O_HP   = 0;
static constexpr size_t O_HS   = O_HP   + NPROW * DPq;
static constexpr size_t O_MOD1 = O_HS   + NSROW * DSq;
static constexpr size_t O_MOD2 = O_MOD1 + (size_t)Bq * 3 * DSq;
static constexpr size_t O_QP   = O_MOD2 + (size_t)Bq * 3 * DSq;
static constexpr size_t O_QS   = O_QP   + NPROW * (size_t)(Hq*HDq);
static constexpr size_t O_KP   = O_QS   + NSROW * (size_t)(Hq*HDq);
static constexpr size_t O_KS   = O_KP   + NPROW * HDq;
static constexpr size_t O_VP   = O_KS   + NSROW * HDq;
static constexpr size_t O_VS   = O_VP   + NPROW * HDq;
static constexpr size_t O_Q    = O_VS   + NSROW * HDq;
static constexpr size_t O_K    = O_Q    + (size_t)Bq*Hq*NTq*HDq;
static constexpr size_t O_VT   = O_K    + (size_t)Bq*NTq*HDq;
static constexpr size_t O_SC   = O_VT   + (size_t)Bq*NTq*HDq;
static constexpr size_t O_AP   = O_SC   + (size_t)Bq*Hq*NTq*NTq;
static constexpr size_t O_AS   = O_AP   + NPROW * (size_t)(Hq*HDq);
static constexpr size_t O_RESP = O_AS   + NSROW * (size_t)(Hq*HDq);
static constexpr size_t O_HP2  = O_RESP + NPROW * DPq;
static constexpr size_t O_RESS = O_HP2  + NPROW * DPq;
static constexpr size_t O_H2S  = O_RESS + NSROW * DSq;
static constexpr size_t O_UP   = O_H2S  + NSROW * DSq;
static constexpr size_t O_HPM  = O_UP   + NPROW * FPq;
static constexpr size_t O_US   = O_HPM  + NPROW * FPq;
static constexpr size_t O_HSM  = O_US   + NSROW * FSq;
static constexpr size_t SCR_TOTAL = O_HSM + NSROW * FSq;

__device__ float g_scr[SCR_TOTAL];

// ---------------- helpers ----------------
__device__ __forceinline__ uint32_t smem_u32(const void* p) {
    uint32_t a;
    asm("{ .reg .u64 t; cvta.to.shared.u64 t, %1; cvt.u32.u64 %0, t; }" : "=r"(a) : "l"(p));
    return a;
}
__device__ __forceinline__ uint32_t lds_b32(uint32_t addr) {
    uint32_t v;
    asm volatile("ld.shared.b32 %0, [%1];" : "=r"(v) : "r"(addr));
    return v;
}
__device__ __forceinline__ void sts_v2(uint32_t addr, uint32_t x, uint32_t y) {
    asm volatile("st.shared.v2.b32 [%0], {%1, %2};" :: "r"(addr), "r"(x), "r"(y) : "memory");
}

__device__ __forceinline__ float gelu_tanh(float x) {
    float x3 = x * x * x;
    return 0.5f * x * (1.0f + tanhf(0.7978845608028654f * (x + 0.044715f * x3)));
}

// split float pair into packed bf16 hi and lo
__device__ __forceinline__ void split2(float x, float y, uint32_t& hi, uint32_t& lo) {
    __nv_bfloat16 hx = __float2bfloat16_rn(x);
    __nv_bfloat16 hy = __float2bfloat16_rn(y);
    float rx = x - __bfloat162float(hx);
    float ry = y - __bfloat162float(hy);
    __nv_bfloat16 lx = __float2bfloat16_rn(rx);
    __nv_bfloat16 ly = __float2bfloat16_rn(ry);
    hi = (uint32_t)__bfloat16_as_ushort(hx) | ((uint32_t)__bfloat16_as_ushort(hy) << 16);
    lo = (uint32_t)__bfloat16_as_ushort(lx) | ((uint32_t)__bfloat16_as_ushort(ly) << 16);
}

#define MMA_BF16(d, a, b) \
    asm volatile("mma.sync.aligned.m16n8k16.row.col.f32.bf16.bf16.f32 " \
        "{%0,%1,%2,%3}, {%4,%5,%6,%7}, {%8,%9}, {%0,%1,%2,%3};" \
        : "+f"((d)[0]), "+f"((d)[1]), "+f"((d)[2]), "+f"((d)[3]) \
        : "r"((a)[0]), "r"((a)[1]), "r"((a)[2]), "r"((a)[3]), "r"((b)[0]), "r"((b)[1]))

struct EpiParams {
    const float* resid;
    const float* gate;
    const float* umat;
    float* outp;
    float* outs;
    float scale;
    int ldg;
    int rpb;
};

// ---------------- mma.sync bf16x3 NT GEMM: C[M,N] = A[M,K] @ B[N,K]^T --------
// Block tile 128x128x32, 8 warps (4 m x 2 n), warp tile 32x64.
// SMEM slot: A_hi/A_lo/B_hi/B_lo, each 128 rows x 32 bf16, padded stride 40 bf16.
#define SROW 80                     // bytes per padded row (40 bf16)
#define SUB  (128 * SROW)           // 10240 B
#define OFF_AH 0
#define OFF_AL (1 * SUB)
#define OFF_BH (2 * SUB)
#define OFF_BL (3 * SUB)
#define SLOT   (4 * SUB)            // 40960 B
#define MM_SMEM (2 * SLOT)          // 81920 B

// Modes: 0 plain; 1 scale+mask; 2 PV scatter; 4 +resid; 5 resid+acc*gate; 6 gelu*U
template <int MODE>
__global__ void __launch_bounds__(256, 1) mgemm(
    const float* __restrict__ Ag, const float* __restrict__ Bg,
    float* __restrict__ Cg, int M, int N, int K,
    long long sAz, long long sBz, int bDivB, long long sCz, EpiParams ep)
{
    extern __shared__ char smem_raw[];
    uint32_t sbase = smem_u32(smem_raw);

    int tid = threadIdx.x;
    int wid = tid >> 5, lane = tid & 31;
    int g = lane >> 2, t4 = lane & 3;
    int wm = wid & 3, wn = wid >> 1 >> 1;     // wm 0..3, wn 0..1
    wn = wid >> 2;
    int z = blockIdx.z;
    const float* A = Ag + (size_t)z * (size_t)sAz;
    const float* B = Bg + (size_t)(z / bDivB) * (size_t)sBz;
    int m0 = blockIdx.y * 128;
    int n0 = blockIdx.x * 128;

    // per-thread staging coordinates: idx = it*256+tid -> row=idx>>3, q=idx&7
    int srow = tid >> 3;            // base row for it=0 (rows advance by 32 per it)
    int sq   = tid & 7;             // float4 index within 32-float row

    float acc[2][8][4];
#pragma unroll
    for (int a = 0; a < 2; a++)
#pragma unroll
        for (int b = 0; b < 8; b++)
#pragma unroll
            for (int c = 0; c < 4; c++) acc[a][b][c] = 0.0f;

    float4 pa[4], pb[4];
    int nc = (K + 31) / 32;

    auto load_chunk = [&](int c) {
        int k0 = c * 32;
        int gk = k0 + sq * 4;
        bool kok = (gk < K);
#pragma unroll
        for (int it = 0; it < 4; ++it) {
            int row = srow + it * 32;
            int gr = m0 + row;
            pa[it] = (kok && gr < M) ? *reinterpret_cast<const float4*>(A + (size_t)gr * K + gk)
                                     : make_float4(0.f, 0.f, 0.f, 0.f);
            int gn = n0 + row;
            pb[it] = (kok && gn < N) ? *reinterpret_cast<const float4*>(B + (size_t)gn * K + gk)
                                     : make_float4(0.f, 0.f, 0.f, 0.f);
        }
    };
    auto store_chunk = [&](int slot) {
        uint32_t sb = sbase + slot * SLOT;
#pragma unroll
        for (int it = 0; it < 4; ++it) {
            int row = srow + it * 32;
            uint32_t off = (uint32_t)(row * SROW + sq * 8);
            uint32_t h0, l0, h1, l1;
            split2(pa[it].x, pa[it].y, h0, l0);
            split2(pa[it].z, pa[it].w, h1, l1);
            sts_v2(sb + OFF_AH + off, h0, h1);
            sts_v2(sb + OFF_AL + off, l0, l1);
            split2(pb[it].x, pb[it].y, h0, l0);
            split2(pb[it].z, pb[it].w, h1, l1);
            sts_v2(sb + OFF_BH + off, h0, h1);
            sts_v2(sb + OFF_BL + off, l0, l1);
        }
    };

    load_chunk(0);
    store_chunk(0);
    __syncthreads();

    for (int c = 0; c < nc; ++c) {
        if (c + 1 < nc) load_chunk(c + 1);

        uint32_t sb = sbase + (c & 1) * SLOT;
#pragma unroll
        for (int kk = 0; kk < 2; ++kk) {
            int kb = kk * 16;
            uint32_t koff0 = (uint32_t)((kb + t4 * 2) * 2);
            uint32_t koff1 = koff0 + 16;
            uint32_t ah[2][4], al[2][4], bb[8][2];
#pragma unroll
            for (int mt = 0; mt < 2; ++mt) {
                uint32_t rb = (uint32_t)((wm * 32 + mt * 16 + g) * SROW);
                ah[mt][0] = lds_b32(sb + OFF_AH + rb + koff0);
                ah[mt][1] = lds_b32(sb + OFF_AH + rb + 8 * SROW + koff0);
                ah[mt][2] = lds_b32(sb + OFF_AH + rb + koff1);
                ah[mt][3] = lds_b32(sb + OFF_AH + rb + 8 * SROW + koff1);
            }
#pragma unroll
            for (int j = 0; j < 8; ++j) {
                uint32_t nb = (uint32_t)((wn * 64 + j * 8 + g) * SROW);
                bb[j][0] = lds_b32(sb + OFF_BH + nb + koff0);
                bb[j][1] = lds_b32(sb + OFF_BH + nb + koff1);
            }
#pragma unroll
            for (int mt = 0; mt < 2; ++mt)
#pragma unroll
                for (int j = 0; j < 8; ++j) MMA_BF16(acc[mt][j], ah[mt], bb[j]);
#pragma unroll
            for (int mt = 0; mt < 2; ++mt) {
                uint32_t rb = (uint32_t)((wm * 32 + mt * 16 + g) * SROW);
                al[mt][0] = lds_b32(sb + OFF_AL + rb + koff0);
                al[mt][1] = lds_b32(sb + OFF_AL + rb + 8 * SROW + koff0);
                al[mt][2] = lds_b32(sb + OFF_AL + rb + koff1);
                al[mt][3] = lds_b32(sb + OFF_AL + rb + 8 * SROW + koff1);
            }
#pragma unroll
            for (int mt = 0; mt < 2; ++mt)
#pragma unroll
                for (int j = 0; j < 8; ++j) MMA_BF16(acc[mt][j], al[mt], bb[j]);
#pragma unroll
            for (int j = 0; j < 8; ++j) {
                uint32_t nb = (uint32_t)((wn * 64 + j * 8 + g) * SROW);
                bb[j][0] = lds_b32(sb + OFF_BL + nb + koff0);
                bb[j][1] = lds_b32(sb + OFF_BL + nb + koff1);
            }
#pragma unroll
            for (int mt = 0; mt < 2; ++mt)
#pragma unroll
                for (int j = 0; j < 8; ++j) MMA_BF16(acc[mt][j], ah[mt], bb[j]);
        }

        if (c + 1 < nc) store_chunk((c + 1) & 1);
        __syncthreads();
    }

    // ---------------- epilogue (accumulators in registers) ----------------
#pragma unroll
    for (int mt = 0; mt < 2; ++mt) {
#pragma unroll
        for (int half = 0; half < 2; ++half) {
            int r = m0 + wm * 32 + mt * 16 + g + half * 8;
            if (r >= M) continue;
#pragma unroll
            for (int j = 0; j < 8; ++j) {
                int cc = n0 + wn * 64 + j * 8 + t4 * 2;
                if (cc >= N) continue;
                float v0 = acc[mt][j][half * 2 + 0];
                float v1 = acc[mt][j][half * 2 + 1];
                size_t idx = (size_t)r * N + cc;
                if constexpr (MODE == 0) {
                    *reinterpret_cast<float2*>(Cg + (size_t)z * sCz + idx) = make_float2(v0, v1);
                } else if constexpr (MODE == 1) {
                    float m0v = (r < SPq && cc >= SPq) ? MASKV : 0.0f;
                    float m1v = (r < SPq && cc + 1 >= SPq) ? MASKV : 0.0f;
                    *reinterpret_cast<float2*>(Cg + (size_t)z * sCz + idx) =
                        make_float2(v0 * ep.scale + m0v, v1 * ep.scale + m1v);
                } else if constexpr (MODE == 2) {
                    int b_ = z / bDivB, h_ = z % bDivB;
                    float* dst = (r < SPq)
                        ? ep.outp + ((size_t)b_ * SPq + r) * (Hq * HDq) + h_ * HDq + cc
                        : ep.outs + ((size_t)b_ * SSq + (r - SPq)) * (Hq * HDq) + h_ * HDq + cc;
                    *reinterpret_cast<float2*>(dst) = make_float2(v0, v1);
                } else if constexpr (MODE == 4) {
                    float2 rs = *reinterpret_cast<const float2*>(ep.resid + idx);
                    *reinterpret_cast<float2*>(Cg + idx) = make_float2(rs.x + v0, rs.y + v1);
                } else if constexpr (MODE == 5) {
                    float2 rs = *reinterpret_cast<const float2*>(ep.resid + idx);
                    const float* gt = ep.gate + (size_t)(r / ep.rpb) * ep.ldg + cc;
                    *reinterpret_cast<float2*>(Cg + idx) =
                        make_float2(rs.x + v0 * gt[0], rs.y + v1 * gt[1]);
                } else if constexpr (MODE == 6) {
                    float2 um = *reinterpret_cast<const float2*>(ep.umat + idx);
                    *reinterpret_cast<float2*>(Cg + idx) =
                        make_float2(gelu_tanh(v0) * um.x, gelu_tanh(v1) * um.y);
                }
            }
        }
    }
}

// ---------------- small SIMT GEMM for cond modulation (M=8) -----------------
__global__ void __launch_bounds__(256) gemm_bias(
    const float* __restrict__ A, const float* __restrict__ B,
    const float* __restrict__ bias, float* __restrict__ C, int M, int N, int K)
{
    __shared__ float As[8][128];
    __shared__ float Bs[8][128];
    int m0 = blockIdx.y * 128, n0 = blockIdx.x * 128;
    int tid = threadIdx.x, tx = tid & 15, ty = tid >> 4;
    int ldRow = tid >> 1, ldCol = (tid & 1) * 4;
    float acc[8][8];
#pragma unroll
    for (int i = 0; i < 8; i++)
#pragma unroll
        for (int j = 0; j < 8; j++) acc[i][j] = 0.0f;
    for (int k0 = 0; k0 < K; k0 += 8) {
        float4 av = make_float4(0.f, 0.f, 0.f, 0.f);
        if (m0 + ldRow < M) av = *reinterpret_cast<const float4*>(A + (size_t)(m0 + ldRow) * K + k0 + ldCol);
        As[ldCol + 0][ldRow] = av.x; As[ldCol + 1][ldRow] = av.y;
        As[ldCol + 2][ldRow] = av.z; As[ldCol + 3][ldRow] = av.w;
        float4 bv = make_float4(0.f, 0.f, 0.f, 0.f);
        if (n0 + ldRow < N) bv = *reinterpret_cast<const float4*>(B + (size_t)(n0 + ldRow) * K + k0 + ldCol);
        Bs[ldCol + 0][ldRow] = bv.x; Bs[ldCol + 1][ldRow] = bv.y;
        Bs[ldCol + 2][ldRow] = bv.z; Bs[ldCol + 3][ldRow] = bv.w;
        __syncthreads();
#pragma unroll
        for (int kk = 0; kk < 8; kk++) {
            float a[8], b[8];
#pragma unroll
            for (int i = 0; i < 8; i++) a[i] = As[kk][ty * 8 + i];
#pragma unroll
            for (int j = 0; j < 8; j++) b[j] = Bs[kk][tx * 8 + j];
#pragma unroll
            for (int i = 0; i < 8; i++)
#pragma unroll
                for (int j = 0; j < 8; j++) acc[i][j] += a[i] * b[j];
        }
        __syncthreads();
    }
#pragma unroll
    for (int i = 0; i < 8; i++) {
        int r = m0 + ty * 8 + i;
        if (r >= M) continue;
#pragma unroll
        for (int j = 0; j < 8; j++) {
            int c = n0 + tx * 8 + j;
            if (c >= N) continue;
            C[(size_t)r * N + c] = acc[i][j] + bias[c];
        }
    }
}

// ---------------- norms ----------------
__global__ void rmsnorm_gemma_k(const float* __restrict__ x, const float* __restrict__ w,
                                float* __restrict__ out, int D)
{
    int row = blockIdx.x;
    const float* xr = x + (size_t)row * D;
    float ss = 0.0f;
    for (int c = threadIdx.x; c < D; c += 256) { float v = xr[c]; ss += v * v; }
    __shared__ float red[256];
    red[threadIdx.x] = ss; __syncthreads();
    for (int s = 128; s > 0; s >>= 1) {
        if (threadIdx.x < s) red[threadIdx.x] += red[threadIdx.x + s];
        __syncthreads();
    }
    float rinv = rsqrtf(red[0] / (float)D + EPSq);
    float* orow = out + (size_t)row * D;
    for (int c = threadIdx.x; c < D; c += 256)
        orow[c] = xr[c] * rinv * (1.0f + w[c]);
}

__global__ void ada_norm_k(const float* __restrict__ x, const float* __restrict__ mod,
                           float* __restrict__ out, int D, int rowsPerB)
{
    int row = blockIdx.x;
    int b = row / rowsPerB;
    const float* xr = x + (size_t)row * D;
    float ss = 0.0f;
    for (int c = threadIdx.x; c < D; c += 256) { float v = xr[c]; ss += v * v; }
    __shared__ float red[256];
    red[threadIdx.x] = ss; __syncthreads();
    for (int s = 128; s > 0; s >>= 1) {
        if (threadIdx.x < s) red[threadIdx.x] += red[threadIdx.x + s];
        __syncthreads();
    }
    float rinv = rsqrtf(red[0] / (float)D + EPSq);
    const float* mb = mod + (size_t)b * 3 * D;
    float* orow = out + (size_t)row * D;
    for (int c = threadIdx.x; c < D; c += 256) {
        float scale = mb[c], shift = mb[D + c];
        orow[c] = xr[c] * rinv * (1.0f + scale) + shift;
    }
}

// ---------------- rope / transpose ----------------
__global__ void rope_q_k(const float* __restrict__ qp, const float* __restrict__ qs,
                         float* __restrict__ q)
{
    size_t idx = (size_t)blockIdx.x * blockDim.x + threadIdx.x;
    const size_t total = (size_t)Bq * NTq * Hq * (HDq / 2);
    if (idx >= total) return;
    int d = (int)(idx % (HDq / 2)); size_t t = idx / (HDq / 2);
    int h = (int)(t % Hq); t /= Hq;
    int n = (int)(t % NTq); int b = (int)(t / NTq);
    const float* src = (n < SPq)
        ? qp + ((size_t)b * SPq + n) * (Hq * HDq) + h * HDq
        : qs + ((size_t)b * SSq + (n - SPq)) * (Hq * HDq) + h * HDq;
    float x1 = src[d], x2 = src[d + 128];
    float invf = powf(10000.0f, -(float)d * (1.0f / 128.0f));
    float ang = (float)n * invf;
    float cs = cosf(ang), sn = sinf(ang);
    float* dst = q + (((size_t)b * Hq + h) * NTq + n) * HDq;
    dst[d] = x1 * cs - x2 * sn;
    dst[d + 128] = x2 * cs + x1 * sn;
}

__global__ void rope_k_k(const float* __restrict__ kp, const float* __restrict__ ks,
                         float* __restrict__ k)
{
    size_t idx = (size_t)blockIdx.x * blockDim.x + threadIdx.x;
    const size_t total = (size_t)Bq * NTq * (HDq / 2);
    if (idx >= total) return;
    int d = (int)(idx % (HDq / 2)); size_t t = idx / (HDq / 2);
    int n = (int)(t % NTq); int b = (int)(t / NTq);
    const float* src = (n < SPq)
        ? kp + ((size_t)b * SPq + n) * HDq
        : ks + ((size_t)b * SSq + (n - SPq)) * HDq;
    float x1 = src[d], x2 = src[d + 128];
    float invf = powf(10000.0f, -(float)d * (1.0f / 128.0f));
    float ang = (float)n * invf;
    float cs = cosf(ang), sn = sinf(ang);
    float* dst = k + ((size_t)b * NTq + n) * HDq;
    dst[d] = x1 * cs - x2 * sn;
    dst[d + 128] = x2 * cs + x1 * sn;
}

__global__ void transpose_v_k(const float* __restrict__ vp, const float* __restrict__ vs,
                              float* __restrict__ vt)
{
    size_t idx = (size_t)blockIdx.x * blockDim.x + threadIdx.x;
    const size_t total = (size_t)Bq * NTq * HDq;
    if (idx >= total) return;
    int d = (int)(idx % HDq); size_t t = idx / HDq;
    int n = (int)(t % NTq); int b = (int)(t / NTq);
    float v = (n < SPq)
        ? vp[((size_t)b * SPq + n) * HDq + d]
        : vs[((size_t)b * SSq + (n - SPq)) * HDq + d];
    vt[((size_t)b * HDq + d) * NTq + n] = v;
}

// ---------------- softmax ----------------
__global__ void softmax_k(float* __restrict__ s, int L)
{
    float* row = s + (size_t)blockIdx.x * L;
    __shared__ float red[256];
    float mx = -INFINITY;
    for (int c = threadIdx.x; c < L; c += 256) mx = fmaxf(mx, row[c]);
    red[threadIdx.x] = mx; __syncthreads();
    for (int st = 128; st > 0; st >>= 1) {
        if (threadIdx.x < st) red[threadIdx.x] = fmaxf(red[threadIdx.x], red[threadIdx.x + st]);
        __syncthreads();
    }
    mx = red[0]; __syncthreads();
    float sum = 0.0f;
    for (int c = threadIdx.x; c < L; c += 256) {
        float e = expf(row[c] - mx);
        row[c] = e; sum += e;
    }
    red[threadIdx.x] = sum; __syncthreads();
    for (int st = 128; st > 0; st >>= 1) {
        if (threadIdx.x < st) red[threadIdx.x] += red[threadIdx.x + st];
        __syncthreads();
    }
    float inv = 1.0f / red[0];
    for (int c = threadIdx.x; c < L; c += 256) row[c] *= inv;
}

// ---------------- host-side dispatch ----------------
static void run_mm(int mode, const float* A, const float* B, float* C,
                   int M, int N, int K,
                   long long sAz, long long sBz, int bDivB, long long sCz,
                   int Z, EpiParams ep)
{
    dim3 grid((N + 127) / 128, (M + 127) / 128, Z);
    switch (mode) {
        case 0:
            cudaFuncSetAttribute(mgemm<0>, cudaFuncAttributeMaxDynamicSharedMemorySize, MM_SMEM);
            mgemm<0><<<grid, 256, MM_SMEM>>>(A, B, C, M, N, K, sAz, sBz, bDivB, sCz, ep); break;
        case 1:
            cudaFuncSetAttribute(mgemm<1>, cudaFuncAttributeMaxDynamicSharedMemorySize, MM_SMEM);
            mgemm<1><<<grid, 256, MM_SMEM>>>(A, B, C, M, N, K, sAz, sBz, bDivB, sCz, ep); break;
        case 2:
            cudaFuncSetAttribute(mgemm<2>, cudaFuncAttributeMaxDynamicSharedMemorySize, MM_SMEM);
            mgemm<2><<<grid, 256, MM_SMEM>>>(A, B, C, M, N, K, sAz, sBz, bDivB, sCz, ep); break;
        case 4:
            cudaFuncSetAttribute(mgemm<4>, cudaFuncAttributeMaxDynamicSharedMemorySize, MM_SMEM);
            mgemm<4><<<grid, 256, MM_SMEM>>>(A, B, C, M, N, K, sAz, sBz, bDivB, sCz, ep); break;
        case 5:
            cudaFuncSetAttribute(mgemm<5>, cudaFuncAttributeMaxDynamicSharedMemorySize, MM_SMEM);
            mgemm<5><<<grid, 256, MM_SMEM>>>(A, B, C, M, N, K, sAz, sBz, bDivB, sCz, ep); break;
        case 6:
            cudaFuncSetAttribute(mgemm<6>, cudaFuncAttributeMaxDynamicSharedMemorySize, MM_SMEM);
            mgemm<6><<<grid, 256, MM_SMEM>>>(A, B, C, M, N, K, sAz, sBz, bDivB, sCz, ep); break;
    }
}

extern "C" void kernel_launch(void* const* d_in, const int* in_sizes, int n_in,
                              void* d_out, int out_size)
{
    const float* prefix_x    = (const float*)d_in[0];
    const float* suffix_x    = (const float*)d_in[1];
    const float* cond        = (const float*)d_in[2];
    const float* p_ln_w      = (const float*)d_in[3];
    const float* p_q_w       = (const float*)d_in[4];
    const float* p_k_w       = (const float*)d_in[5];
    const float* p_v_w       = (const float*)d_in[6];
    const float* p_o_w       = (const float*)d_in[7];
    const float* p_post_ln_w = (const float*)d_in[8];
    const float* p_gate_w    = (const float*)d_in[9];
    const float* p_up_w      = (const float*)d_in[10];
    const float* p_down_w    = (const float*)d_in[11];
    const float* s_ada1_w    = (const float*)d_in[12];
    const float* s_ada1_b    = (const float*)d_in[13];
    const float* s_q_w       = (const float*)d_in[14];
    const float* s_k_w       = (const float*)d_in[15];
    const float* s_v_w       = (const float*)d_in[16];
    const float* s_o_w       = (const float*)d_in[17];
    const float* s_ada2_w    = (const float*)d_in[18];
    const float* s_ada2_b    = (const float*)d_in[19];
    const float* s_gate_w    = (const float*)d_in[20];
    const float* s_up_w      = (const float*)d_in[21];
    const float* s_down_w    = (const float*)d_in[22];

    float* scr = nullptr;
    cudaGetSymbolAddress((void**)&scr, g_scr);

    float* hp    = scr + O_HP;
    float* hs    = scr + O_HS;
    float* mod1  = scr + O_MOD1;
    float* mod2  = scr + O_MOD2;
    float* qp    = scr + O_QP;
    float* qs    = scr + O_QS;
    float* kp    = scr + O_KP;
    float* ks    = scr + O_KS;
    float* vp    = scr + O_VP;
    float* vs    = scr + O_VS;
    float* q     = scr + O_Q;
    float* k     = scr + O_K;
    float* vt    = scr + O_VT;
    float* sc    = scr + O_SC;
    float* ap    = scr + O_AP;
    float* as_   = scr + O_AS;
    float* res_p = scr + O_RESP;
    float* hp2   = scr + O_HP2;
    float* res_s = scr + O_RESS;
    float* h2s   = scr + O_H2S;
    float* Up    = scr + O_UP;
    float* Hp    = scr + O_HPM;
    float* Us    = scr + O_US;
    float* Hs    = scr + O_HSM;

    float* outp = (float*)d_out;
    float* outs = outp + NPROW * DPq;

    EpiParams ep0 = {};

    // 1) norms + ada modulation
    rmsnorm_gemma_k<<<(int)NPROW, 256>>>(prefix_x, p_ln_w, hp, DPq);
    gemm_bias<<<dim3(24, 1, 1), 256>>>(cond, s_ada1_w, s_ada1_b, mod1, Bq, 3 * DSq, DCq);
    ada_norm_k<<<(int)NSROW, 256>>>(suffix_x, mod1, hs, DSq, SSq);

    // 2) QKV projections
    run_mm(0, hp, p_q_w, qp, (int)NPROW, Hq * HDq, DPq, 0, 0, 1, 0, 1, ep0);
    run_mm(0, hp, p_k_w, kp, (int)NPROW, HDq,      DPq, 0, 0, 1, 0, 1, ep0);
    run_mm(0, hp, p_v_w, vp, (int)NPROW, HDq,      DPq, 0, 0, 1, 0, 1, ep0);
    run_mm(0, hs, s_q_w, qs, (int)NSROW, Hq * HDq, DSq, 0, 0, 1, 0, 1, ep0);
    run_mm(0, hs, s_k_w, ks, (int)NSROW, HDq,      DSq, 0, 0, 1, 0, 1, ep0);
    run_mm(0, hs, s_v_w, vs, (int)NSROW, HDq,      DSq, 0, 0, 1, 0, 1, ep0);

    // 3) RoPE + layouts
    {
        size_t tq = (size_t)Bq * NTq * Hq * (HDq / 2);
        rope_q_k<<<(int)((tq + 255) / 256), 256>>>(qp, qs, q);
        size_t tk = (size_t)Bq * NTq * (HDq / 2);
        rope_k_k<<<(int)((tk + 255) / 256), 256>>>(kp, ks, k);
        size_t tv = (size_t)Bq * NTq * HDq;
        transpose_v_k<<<(int)((tv + 255) / 256), 256>>>(vp, vs, vt);
    }

    // 4) attention
    { EpiParams e = ep0; e.scale = 0.0625f;
      run_mm(1, q, k, sc, NTq, NTq, HDq,
             (long long)NTq * HDq, (long long)NTq * HDq, Hq,
             (long long)NTq * NTq, Bq * Hq, e); }
    softmax_k<<<Bq * Hq * NTq, 256>>>(sc, NTq);
    { EpiParams e = ep0; e.outp = ap; e.outs = as_;
      run_mm(2, sc, vt, nullptr, NTq, HDq, NTq,
             (long long)NTq * NTq, (long long)HDq * NTq, Hq, 0, Bq * Hq, e); }

    // 5) prefix: o-proj + residual, post-norm, MLP
    { EpiParams e = ep0; e.resid = prefix_x;
      run_mm(4, ap, p_o_w, res_p, (int)NPROW, DPq, Hq * HDq, 0, 0, 1, 0, 1, e); }
    rmsnorm_gemma_k<<<(int)NPROW, 256>>>(res_p, p_post_ln_w, hp2, DPq);
    run_mm(0, hp2, p_up_w, Up, (int)NPROW, FPq, DPq, 0, 0, 1, 0, 1, ep0);
    { EpiParams e = ep0; e.umat = Up;
      run_mm(6, hp2, p_gate_w, Hp, (int)NPROW, FPq, DPq, 0, 0, 1, 0, 1, e); }
    { EpiParams e = ep0; e.resid = res_p;
      run_mm(4, Hp, p_down_w, outp, (int)NPROW, DPq, FPq, 0, 0, 1, 0, 1, e); }

    // 6) suffix: gated o-proj + residual, ada-norm2, gated MLP
    { EpiParams e = ep0; e.resid = suffix_x; e.gate = mod1 + 2 * DSq; e.ldg = 3 * DSq; e.rpb = SSq;
      run_mm(5, as_, s_o_w, res_s, (int)NSROW, DSq, Hq * HDq, 0, 0, 1, 0, 1, e); }
    gemm_bias<<<dim3(24, 1, 1), 256>>>(cond, s_ada2_w, s_ada2_b, mod2, Bq, 3 * DSq, DCq);
    ada_norm_k<<<(int)NSROW, 256>>>(res_s, mod2, h2s, DSq, SSq);
    run_mm(0, h2s, s_up_w, Us, (int)NSROW, FSq, DSq, 0, 0, 1, 0, 1, ep0);
    { EpiParams e = ep0; e.umat = Us;
      run_mm(6, h2s, s_gate_w, Hs, (int)NSROW, FSq, DSq, 0, 0, 1, 0, 1, e); }
    { EpiParams e = ep0; e.resid = res_s; e.gate = mod2 + 2 * DSq; e.ldg = 3 * DSq; e.rpb = SSq;
      run_mm(5, Hs, s_down_w, outs, (int)NSROW, DSq, FSq, 0, 0, 1, 0, 1, e); }
}